// round 4
// baseline (speedup 1.0000x reference)
#include <cuda_runtime.h>
#include <cstdint>

#define NUM_CLASSES 7
#define NBLOCKS 1184      // 148 SMs * 8
#define NTHREADS 256

__device__ float g_partials[NBLOCKS];
__device__ unsigned int g_done_count = 0;

__global__ __launch_bounds__(NTHREADS)
void hinge_fused_kernel(const float4* __restrict__ logit4,
                        const int4* __restrict__ label4,
                        const int4* __restrict__ repr4,
                        const float* __restrict__ logit_s,
                        const int* __restrict__ label_s,
                        const int* __restrict__ repr_s,
                        int ngroups, int tail_start, int B,
                        float* __restrict__ out)
{
    float acc = 0.0f;
    const int stride = gridDim.x * blockDim.x;

    for (int g = blockIdx.x * blockDim.x + threadIdx.x; g < ngroups; g += stride) {
        // labels: 4 rows, one LDG.128
        int4 lab = __ldcs(label4 + g);
        const int* lb = reinterpret_cast<const int*>(&lab);

        // repr_num: 4 rows * 3 int32 = 48 B = 3x LDG.128
        int4 r[3];
        #pragma unroll
        for (int i = 0; i < 3; i++)
            r[i] = __ldcs(repr4 + (size_t)g * 3 + i);
        const int* rv = reinterpret_cast<const int*>(r);

        // logits: 4 rows * 7 fp32 = 112 B = 7x LDG.128
        float4 L[7];
        #pragma unroll
        for (int i = 0; i < 7; i++)
            L[i] = __ldcs(logit4 + (size_t)g * 7 + i);
        const float* lf = reinterpret_cast<const float*>(L);

        #pragma unroll
        for (int row = 0; row < 4; row++) {
            unsigned mask = (1u << rv[row * 3 + 0])
                          | (1u << rv[row * 3 + 1])
                          | (1u << rv[row * 3 + 2]);
            float t = (lb[row] == 1) ? 1.0f : 0.0f;
            #pragma unroll
            for (int j = 0; j < NUM_CLASSES; j++) {
                float d = lf[row * NUM_CLASSES + j] - t;
                acc += ((mask >> j) & 1u) ? fabsf(d) : fmaxf(d, 0.0f);
            }
        }
    }

    // tail rows (B not multiple of 4)
    if (blockIdx.x == 0 && threadIdx.x == 0) {
        for (int row = tail_start; row < B; row++) {
            unsigned mask = (1u << repr_s[(size_t)row * 3 + 0])
                          | (1u << repr_s[(size_t)row * 3 + 1])
                          | (1u << repr_s[(size_t)row * 3 + 2]);
            float t = (label_s[row] == 1) ? 1.0f : 0.0f;
            for (int j = 0; j < NUM_CLASSES; j++) {
                float d = logit_s[(size_t)row * NUM_CLASSES + j] - t;
                acc += ((mask >> j) & 1u) ? fabsf(d) : fmaxf(d, 0.0f);
            }
        }
    }

    // intra-block reduce
    #pragma unroll
    for (int o = 16; o > 0; o >>= 1)
        acc += __shfl_down_sync(0xffffffffu, acc, o);

    __shared__ float s[NTHREADS / 32];
    __shared__ bool is_last;
    if ((threadIdx.x & 31) == 0) s[threadIdx.x >> 5] = acc;
    __syncthreads();

    if (threadIdx.x < (NTHREADS / 32)) {
        float v = s[threadIdx.x];
        #pragma unroll
        for (int o = (NTHREADS / 64); o > 0; o >>= 1)
            v += __shfl_down_sync(0x000000ffu, v, o);
        if (threadIdx.x == 0) {
            g_partials[blockIdx.x] = v;
            __threadfence();
            unsigned int prev = atomicAdd(&g_done_count, 1u);
            is_last = (prev == (unsigned)gridDim.x - 1u);
        }
    }
    __syncthreads();

    // last block to finish performs the deterministic final reduction
    if (is_last) {
        double dacc = 0.0;
        for (int i = threadIdx.x; i < NBLOCKS; i += NTHREADS)
            dacc += (double)g_partials[i];

        #pragma unroll
        for (int o = 16; o > 0; o >>= 1)
            dacc += __shfl_down_sync(0xffffffffu, dacc, o);

        __shared__ double sd[NTHREADS / 32];
        if ((threadIdx.x & 31) == 0) sd[threadIdx.x >> 5] = dacc;
        __syncthreads();

        if (threadIdx.x < (NTHREADS / 32)) {
            double v = sd[threadIdx.x];
            #pragma unroll
            for (int o = (NTHREADS / 64); o > 0; o >>= 1)
                v += __shfl_down_sync(0x000000ffu, v, o);
            if (threadIdx.x == 0) {
                *out = (float)v;
                g_done_count = 0;   // reset for next graph replay
            }
        }
    }
}

extern "C" void kernel_launch(void* const* d_in, const int* in_sizes, int n_in,
                              void* d_out, int out_size)
{
    // logit is [B,7] fp32 at d_in[0] (largest input, 7-multiple element count).
    const float* logit = (const float*)d_in[0];
    const int B = in_sizes[0] / NUM_CLASSES;

    // Disambiguate label ([B] int32) vs repr_num ([B,3] int32) by element count.
    const int* label;
    const int* repr;
    if (in_sizes[1] == B) {
        label = (const int*)d_in[1];
        repr  = (const int*)d_in[2];
    } else {
        label = (const int*)d_in[2];
        repr  = (const int*)d_in[1];
    }

    const int ngroups = B / 4;          // groups of 4 rows (all loads 16B-aligned)
    const int tail_start = ngroups * 4;

    hinge_fused_kernel<<<NBLOCKS, NTHREADS>>>(
        (const float4*)logit, (const int4*)label, (const int4*)repr,
        logit, label, repr, ngroups, tail_start, B, (float*)d_out);
}

// round 5
// speedup vs baseline: 1.1261x; 1.1261x over previous
#include <cuda_runtime.h>
#include <cstdint>

#define NUM_CLASSES 7
#define NBLOCKS 1184      // 148 SMs * 8
#define NTHREADS 256

__device__ double g_sum = 0.0;
__device__ unsigned int g_done_count = 0;

__global__ __launch_bounds__(NTHREADS)
void hinge_fused_kernel(const float4* __restrict__ logit4,
                        const int4* __restrict__ label4,
                        const int4* __restrict__ repr4,
                        const float* __restrict__ logit_s,
                        const int* __restrict__ label_s,
                        const int* __restrict__ repr_s,
                        int ngroups, int tail_start, int B,
                        float* __restrict__ out)
{
    float acc = 0.0f;
    const int stride = gridDim.x * blockDim.x;

    for (int g = blockIdx.x * blockDim.x + threadIdx.x; g < ngroups; g += stride) {
        // labels: 4 rows, one LDG.128
        int4 lab = __ldcs(label4 + g);
        const int* lb = reinterpret_cast<const int*>(&lab);

        // repr_num: 4 rows * 3 int32 = 48 B = 3x LDG.128
        int4 r[3];
        #pragma unroll
        for (int i = 0; i < 3; i++)
            r[i] = __ldcs(repr4 + (size_t)g * 3 + i);
        const int* rv = reinterpret_cast<const int*>(r);

        // logits: 4 rows * 7 fp32 = 112 B = 7x LDG.128
        float4 L[7];
        #pragma unroll
        for (int i = 0; i < 7; i++)
            L[i] = __ldcs(logit4 + (size_t)g * 7 + i);
        const float* lf = reinterpret_cast<const float*>(L);

        #pragma unroll
        for (int row = 0; row < 4; row++) {
            unsigned mask = (1u << rv[row * 3 + 0])
                          | (1u << rv[row * 3 + 1])
                          | (1u << rv[row * 3 + 2]);
            float t = (lb[row] == 1) ? 1.0f : 0.0f;
            #pragma unroll
            for (int j = 0; j < NUM_CLASSES; j++) {
                float d = lf[row * NUM_CLASSES + j] - t;
                acc += ((mask >> j) & 1u) ? fabsf(d) : fmaxf(d, 0.0f);
            }
        }
    }

    // tail rows (B not multiple of 4)
    if (blockIdx.x == 0 && threadIdx.x == 0) {
        for (int row = tail_start; row < B; row++) {
            unsigned mask = (1u << repr_s[(size_t)row * 3 + 0])
                          | (1u << repr_s[(size_t)row * 3 + 1])
                          | (1u << repr_s[(size_t)row * 3 + 2]);
            float t = (label_s[row] == 1) ? 1.0f : 0.0f;
            for (int j = 0; j < NUM_CLASSES; j++) {
                float d = logit_s[(size_t)row * NUM_CLASSES + j] - t;
                acc += ((mask >> j) & 1u) ? fabsf(d) : fmaxf(d, 0.0f);
            }
        }
    }

    // intra-block reduce
    #pragma unroll
    for (int o = 16; o > 0; o >>= 1)
        acc += __shfl_down_sync(0xffffffffu, acc, o);

    __shared__ float s[NTHREADS / 32];
    if ((threadIdx.x & 31) == 0) s[threadIdx.x >> 5] = acc;
    __syncthreads();

    // tiny epilogue: one f64 atomic per block + last-block scalar writeout
    if (threadIdx.x == 0) {
        float v = 0.0f;
        #pragma unroll
        for (int w = 0; w < NTHREADS / 32; w++) v += s[w];

        atomicAdd(&g_sum, (double)v);
        __threadfence();
        unsigned int prev = atomicAdd(&g_done_count, 1u);
        if (prev == (unsigned)gridDim.x - 1u) {
            // all g_sum contributions are visible (each was fenced before its count bump)
            double total = atomicAdd(&g_sum, 0.0);   // L2-coherent read
            *out = (float)total;
            // reset for next graph replay (kernel completion flushes these)
            g_sum = 0.0;
            g_done_count = 0u;
        }
    }
}

extern "C" void kernel_launch(void* const* d_in, const int* in_sizes, int n_in,
                              void* d_out, int out_size)
{
    // logit is [B,7] fp32 at d_in[0] (largest input, 7-multiple element count).
    const float* logit = (const float*)d_in[0];
    const int B = in_sizes[0] / NUM_CLASSES;

    // Disambiguate label ([B] int32) vs repr_num ([B,3] int32) by element count.
    const int* label;
    const int* repr;
    if (in_sizes[1] == B) {
        label = (const int*)d_in[1];
        repr  = (const int*)d_in[2];
    } else {
        label = (const int*)d_in[2];
        repr  = (const int*)d_in[1];
    }

    const int ngroups = B / 4;          // groups of 4 rows (all loads 16B-aligned)
    const int tail_start = ngroups * 4;

    hinge_fused_kernel<<<NBLOCKS, NTHREADS>>>(
        (const float4*)logit, (const int4*)label, (const int4*)repr,
        logit, label, repr, ngroups, tail_start, B, (float*)d_out);
}